// round 1
// baseline (speedup 1.0000x reference)
#include <cuda_runtime.h>
#include <cuda_bf16.h>

// Problem constants
#define B_DIM 16
#define T_DIM 100
#define HW 1296           // 27*48
#define CH 3
#define FRAME_INTS (HW*CH)      // 3888
#define NBINS 512
#define WIN 101
#define HALF 50
#define ODIM 128

// Scratch (device globals — no allocation allowed)
__device__ float g_hist[B_DIM * T_DIM * NBINS];   // 3.28 MB
__device__ float g_sim [B_DIM * T_DIM * T_DIM];   // 640 KB

// ---------------------------------------------------------------------------
// Kernel 1: per-frame 512-bin color histogram + L2 normalize
// One block per frame (1600 blocks, 256 threads)
// ---------------------------------------------------------------------------
__global__ __launch_bounds__(256) void k_hist(const int* __restrict__ frames,
                                              float* __restrict__ hist) {
    __shared__ int stage[FRAME_INTS];   // 15552 B
    __shared__ int sh[NBINS];           // 2048 B
    __shared__ int wsum[8];
    __shared__ float s_inv;

    const int f   = blockIdx.x;
    const int tid = threadIdx.x;

    // Stage the whole frame with coalesced 16B loads (3888 % 4 == 0 -> 972 int4)
    const int4* src = reinterpret_cast<const int4*>(frames + (long long)f * FRAME_INTS);
    int4* dst = reinterpret_cast<int4*>(stage);
    #pragma unroll
    for (int i = tid; i < FRAME_INTS / 4; i += 256) dst[i] = src[i];

    for (int i = tid; i < NBINS; i += 256) sh[i] = 0;
    __syncthreads();

    // Histogram: pixel p at stage[3p..3p+2]; 3p mod 32 cycles all banks (gcd(3,32)=1)
    for (int p = tid; p < HW; p += 256) {
        int r = stage[3*p+0];
        int g = stage[3*p+1];
        int b = stage[3*p+2];
        int bin = ((r >> 5) << 6) | ((g >> 5) << 3) | (b >> 5);
        atomicAdd(&sh[bin], 1);
    }
    __syncthreads();

    // Exact integer sum of squares (<= 1296^2 < 2^31)
    int local = 0;
    for (int i = tid; i < NBINS; i += 256) { int h = sh[i]; local += h * h; }
    #pragma unroll
    for (int o = 16; o; o >>= 1) local += __shfl_down_sync(0xffffffff, local, o);
    if ((tid & 31) == 0) wsum[tid >> 5] = local;
    __syncthreads();
    if (tid == 0) {
        int tot = 0;
        #pragma unroll
        for (int w = 0; w < 8; w++) tot += wsum[w];
        s_inv = 1.0f / sqrtf((float)tot);
    }
    __syncthreads();

    const float inv = s_inv;
    float* out = hist + (long long)f * NBINS;
    for (int i = tid; i < NBINS; i += 256) out[i] = (float)sh[i] * inv;
}

// ---------------------------------------------------------------------------
// Kernel 2: sim[b] = X[b] @ X[b]^T  (X is 100x512), banded + symmetric
// 32x32 output tiles; only ti<=tj tiles (symmetry), skip |ti-tj|==3 (out of band)
// blockIdx.x in [0,9) -> (ti,tj) pair, blockIdx.y = batch. 256 threads.
// ---------------------------------------------------------------------------
__constant__ int c_ti[9] = {0,0,0,1,1,1,2,2,3};
__constant__ int c_tj[9] = {0,1,2,1,2,3,2,3,3};

__global__ __launch_bounds__(256) void k_sim(const float* __restrict__ hist,
                                             float* __restrict__ sim) {
    __shared__ __align__(16) float As[32][36];
    __shared__ __align__(16) float Bs[32][36];

    const int b  = blockIdx.y;
    const int ti = c_ti[blockIdx.x];
    const int tj = c_tj[blockIdx.x];

    const float* X = hist + (long long)b * T_DIM * NBINS;
    const int tid = threadIdx.x;
    const int tx = tid & 31;        // output column within tile
    const int ty = tid >> 5;        // 0..7, owns rows ty*4 .. ty*4+3

    const int row0 = ti * 32;
    const int col0 = tj * 32;

    float acc[4] = {0.f, 0.f, 0.f, 0.f};

    for (int kc = 0; kc < NBINS; kc += 32) {
        // Cooperative load: 1024 elems each, coalesced over k
        #pragma unroll
        for (int l = tid; l < 1024; l += 256) {
            int r = l >> 5, k = l & 31;
            int gr = row0 + r;
            int gc = col0 + r;
            As[r][k] = (gr < T_DIM) ? X[gr * NBINS + kc + k] : 0.f;
            Bs[r][k] = (gc < T_DIM) ? X[gc * NBINS + kc + k] : 0.f;
        }
        __syncthreads();

        const float4* Bs4 = reinterpret_cast<const float4*>(&Bs[tx][0]);
        #pragma unroll
        for (int k4 = 0; k4 < 8; k4++) {
            float4 bv = Bs4[k4];
            #pragma unroll
            for (int u = 0; u < 4; u++) {
                float4 av = *reinterpret_cast<const float4*>(&As[ty*4 + u][k4*4]);
                acc[u] += av.x * bv.x + av.y * bv.y + av.z * bv.z + av.w * bv.w;
            }
        }
        __syncthreads();
    }

    float* S = sim + (long long)b * T_DIM * T_DIM;
    #pragma unroll
    for (int u = 0; u < 4; u++) {
        int r = row0 + ty * 4 + u;
        int c = col0 + tx;
        if (r < T_DIM && c < T_DIM) {
            float v = acc[u];
            S[r * T_DIM + c] = v;
            S[c * T_DIM + r] = v;   // symmetry (diagonal tiles: harmless rewrite)
        }
    }
}

// ---------------------------------------------------------------------------
// Kernel 3: band extraction + FC + ReLU
// Block = (batch, 10 consecutive t). 128 threads, thread owns output dim d.
// fc_w cached in smem in two chunks of 51/50 rows (stays under 48KB static).
// ---------------------------------------------------------------------------
__global__ __launch_bounds__(128) void k_fc(const float* __restrict__ sim,
                                            const float* __restrict__ fc_w,
                                            const float* __restrict__ fc_b,
                                            float* __restrict__ out) {
    __shared__ float w_s[51 * ODIM];     // 26112 B
    __shared__ float band[10][WIN];      //  4040 B

    const int b   = blockIdx.y;
    const int t0  = blockIdx.x * 10;
    const int tid = threadIdx.x;         // = output dim d

    // Load band rows for the 10 t's (zero outside [0,100))
    const float* S = sim + (long long)b * T_DIM * T_DIM;
    for (int i = tid; i < 10 * WIN; i += 128) {
        int tt = i / WIN, s = i - tt * WIN;
        int t  = t0 + tt;
        int t2 = t + s - HALF;
        band[tt][s] = (t2 >= 0 && t2 < T_DIM) ? S[t * T_DIM + t2] : 0.f;
    }

    float acc[10];
    const float bias = fc_b[tid];
    #pragma unroll
    for (int tt = 0; tt < 10; tt++) acc[tt] = bias;

    // Two fc_w chunks: s in [0,51) then [51,101)
    #pragma unroll
    for (int chunk = 0; chunk < 2; chunk++) {
        const int s0 = chunk ? 51 : 0;
        const int ns = chunk ? 50 : 51;
        __syncthreads();   // band ready (1st iter) / previous compute done (2nd)
        for (int j = 0; j < ns; j++)
            w_s[j * ODIM + tid] = fc_w[(s0 + j) * ODIM + tid];
        __syncthreads();

        #pragma unroll
        for (int tt = 0; tt < 10; tt++) {
            float a = acc[tt];
            #pragma unroll 4
            for (int j = 0; j < ns; j++)
                a += band[tt][s0 + j] * w_s[j * ODIM + tid];
            acc[tt] = a;
        }
    }

    float* O = out + ((long long)(b * T_DIM + t0)) * ODIM + tid;
    #pragma unroll
    for (int tt = 0; tt < 10; tt++)
        O[tt * ODIM] = fmaxf(acc[tt], 0.f);
}

// ---------------------------------------------------------------------------
extern "C" void kernel_launch(void* const* d_in, const int* in_sizes, int n_in,
                              void* d_out, int out_size) {
    const int*   frames = (const int*)  d_in[0];
    const float* fc_w   = (const float*)d_in[1];
    const float* fc_b   = (const float*)d_in[2];
    float*       out    = (float*)d_out;

    float* hist;
    float* sim;
    cudaGetSymbolAddress((void**)&hist, g_hist);
    cudaGetSymbolAddress((void**)&sim,  g_sim);

    k_hist<<<B_DIM * T_DIM, 256>>>(frames, hist);
    k_sim <<<dim3(9, B_DIM), 256>>>(hist, sim);
    k_fc  <<<dim3(T_DIM / 10, B_DIM), 128>>>(sim, fc_w, fc_b, out);
}

// round 2
// speedup vs baseline: 1.1174x; 1.1174x over previous
#include <cuda_runtime.h>
#include <cuda_bf16.h>

// Problem constants
#define B_DIM 16
#define T_DIM 100
#define HW 1296           // 27*48
#define FRAME_INTS (HW*3) // 3888
#define NBINS 512
#define WIN 101
#define HALF 50
#define ODIM 128

// Scratch (device globals — no allocation allowed)
__device__ float g_hist[B_DIM * T_DIM * NBINS];   // 3.28 MB
__device__ float g_sim [B_DIM * T_DIM * T_DIM];   // 640 KB

// ---------------------------------------------------------------------------
// Kernel 1: per-frame 512-bin color histogram + L2 normalize
// One block per frame. Direct int4 global loads (4 pixels per 3 int4),
// no smem staging, smem atomics into 512-bin hist.
// ---------------------------------------------------------------------------
__global__ __launch_bounds__(256) void k_hist(const int* __restrict__ frames,
                                              float* __restrict__ hist) {
    __shared__ int sh[NBINS];
    __shared__ int wsum[8];
    __shared__ float s_inv;

    const int f   = blockIdx.x;
    const int tid = threadIdx.x;

    for (int i = tid; i < NBINS; i += 256) sh[i] = 0;
    __syncthreads();

    // 3888 ints = 972 int4 = 324 chunks of 3 int4 (4 pixels each)
    const int4* base = reinterpret_cast<const int4*>(frames + (long long)f * FRAME_INTS);
    for (int c = tid; c < 324; c += 256) {
        int4 a = base[3*c+0];
        int4 b = base[3*c+1];
        int4 d = base[3*c+2];
        int bin0 = ((a.x >> 5) << 6) | ((a.y >> 5) << 3) | (a.z >> 5);
        int bin1 = ((a.w >> 5) << 6) | ((b.x >> 5) << 3) | (b.y >> 5);
        int bin2 = ((b.z >> 5) << 6) | ((b.w >> 5) << 3) | (d.x >> 5);
        int bin3 = ((d.y >> 5) << 6) | ((d.z >> 5) << 3) | (d.w >> 5);
        atomicAdd(&sh[bin0], 1);
        atomicAdd(&sh[bin1], 1);
        atomicAdd(&sh[bin2], 1);
        atomicAdd(&sh[bin3], 1);
    }
    __syncthreads();

    // Exact integer sum of squares (<= 1296^2 < 2^31)
    int local = 0;
    for (int i = tid; i < NBINS; i += 256) { int h = sh[i]; local += h * h; }
    #pragma unroll
    for (int o = 16; o; o >>= 1) local += __shfl_down_sync(0xffffffff, local, o);
    if ((tid & 31) == 0) wsum[tid >> 5] = local;
    __syncthreads();
    if (tid == 0) {
        int tot = 0;
        #pragma unroll
        for (int w = 0; w < 8; w++) tot += wsum[w];
        s_inv = 1.0f / sqrtf((float)tot);
    }
    __syncthreads();

    const float inv = s_inv;
    float* out = hist + (long long)f * NBINS;
    for (int i = tid; i < NBINS; i += 256) out[i] = (float)sh[i] * inv;
}

// ---------------------------------------------------------------------------
// Kernel 2: sim[b] = X[b] @ X[b]^T  (X is 100x512), banded + symmetric
// 32x32 tiles, ti<=tj only (symmetry), |ti-tj|==3 skipped (outside band).
// Software-pipelined: register prefetch + double-buffered smem tiles.
// ---------------------------------------------------------------------------
__constant__ int c_ti[9] = {0,0,0,1,1,1,2,2,3};
__constant__ int c_tj[9] = {0,1,2,1,2,3,2,3,3};

__global__ __launch_bounds__(256) void k_sim(const float* __restrict__ hist,
                                             float* __restrict__ sim) {
    __shared__ __align__(16) float As[2][32][36];
    __shared__ __align__(16) float Bs[2][32][36];

    const int b  = blockIdx.y;
    const int ti = c_ti[blockIdx.x];
    const int tj = c_tj[blockIdx.x];

    const float* X = hist + (long long)b * T_DIM * NBINS;
    const int tid = threadIdx.x;
    const int tx = tid & 31;
    const int ty = tid >> 5;

    const int row0 = ti * 32;
    const int col0 = tj * 32;

    // Per-thread load slots: 4 elements of A-tile + 4 of B-tile
    int rr[4], kk[4];
    bool va[4], vb[4];
    const float* pa[4];
    const float* pb[4];
    #pragma unroll
    for (int j = 0; j < 4; j++) {
        int l = tid + j * 256;
        rr[j] = l >> 5; kk[j] = l & 31;
        va[j] = (row0 + rr[j]) < T_DIM;
        vb[j] = (col0 + rr[j]) < T_DIM;
        pa[j] = X + (row0 + rr[j]) * NBINS + kk[j];
        pb[j] = X + (col0 + rr[j]) * NBINS + kk[j];
    }

    float ra[4], rb[4];
    #pragma unroll
    for (int j = 0; j < 4; j++) {
        ra[j] = va[j] ? pa[j][0] : 0.f;
        rb[j] = vb[j] ? pb[j][0] : 0.f;
    }
    #pragma unroll
    for (int j = 0; j < 4; j++) {
        As[0][rr[j]][kk[j]] = ra[j];
        Bs[0][rr[j]][kk[j]] = rb[j];
    }
    __syncthreads();

    float acc[4] = {0.f, 0.f, 0.f, 0.f};

    #pragma unroll 1
    for (int it = 0; it < 16; it++) {
        const int buf = it & 1;

        // Prefetch next tile into registers (LDG in flight during compute)
        if (it < 15) {
            const int kc = (it + 1) * 32;
            #pragma unroll
            for (int j = 0; j < 4; j++) {
                ra[j] = va[j] ? pa[j][kc] : 0.f;
                rb[j] = vb[j] ? pb[j][kc] : 0.f;
            }
        }

        // Compute on current buffer
        const float* brow = &Bs[buf][tx][0];
        #pragma unroll
        for (int k4 = 0; k4 < 8; k4++) {
            float4 bv = *reinterpret_cast<const float4*>(brow + k4 * 4);
            #pragma unroll
            for (int u = 0; u < 4; u++) {
                float4 av = *reinterpret_cast<const float4*>(&As[buf][ty*4 + u][k4*4]);
                acc[u] += av.x * bv.x + av.y * bv.y + av.z * bv.z + av.w * bv.w;
            }
        }

        if (it < 15) {
            __syncthreads();   // all warps done reading buf^1 from previous iter
            #pragma unroll
            for (int j = 0; j < 4; j++) {
                As[buf ^ 1][rr[j]][kk[j]] = ra[j];
                Bs[buf ^ 1][rr[j]][kk[j]] = rb[j];
            }
            __syncthreads();   // next tile ready
        }
    }

    float* S = sim + (long long)b * T_DIM * T_DIM;
    #pragma unroll
    for (int u = 0; u < 4; u++) {
        int r = row0 + ty * 4 + u;
        int c = col0 + tx;
        if (r < T_DIM && c < T_DIM) {
            float v = acc[u];
            S[r * T_DIM + c] = v;
            S[c * T_DIM + r] = v;   // symmetry
        }
    }
}

// ---------------------------------------------------------------------------
// Kernel 3: band extraction + FC + ReLU
// Block = (batch, 10 consecutive t). 128 threads; thread owns output dim d.
// j-outer loop: 1 weight LDS + 10 broadcast LDS per 10 FFMA.
// ---------------------------------------------------------------------------
__global__ __launch_bounds__(128) void k_fc(const float* __restrict__ sim,
                                            const float* __restrict__ fc_w,
                                            const float* __restrict__ fc_b,
                                            float* __restrict__ out) {
    __shared__ float w_s[51 * ODIM];     // 26112 B
    __shared__ float band[10][WIN];      //  4040 B

    const int b   = blockIdx.y;
    const int t0  = blockIdx.x * 10;
    const int tid = threadIdx.x;

    const float* S = sim + (long long)b * T_DIM * T_DIM;
    for (int i = tid; i < 10 * WIN; i += 128) {
        int tt = i / WIN, s = i - tt * WIN;
        int t  = t0 + tt;
        int t2 = t + s - HALF;
        band[tt][s] = (t2 >= 0 && t2 < T_DIM) ? S[t * T_DIM + t2] : 0.f;
    }

    float acc[10];
    const float bias = fc_b[tid];
    #pragma unroll
    for (int tt = 0; tt < 10; tt++) acc[tt] = bias;

    #pragma unroll
    for (int chunk = 0; chunk < 2; chunk++) {
        const int s0 = chunk ? 51 : 0;
        const int ns = chunk ? 50 : 51;
        __syncthreads();   // band ready (1st) / previous chunk compute done (2nd)
        for (int j = 0; j < ns; j++)
            w_s[j * ODIM + tid] = fc_w[(s0 + j) * ODIM + tid];
        __syncthreads();

        for (int j = 0; j < ns; j++) {
            const float wv = w_s[j * ODIM + tid];
            const int s = s0 + j;
            #pragma unroll
            for (int tt = 0; tt < 10; tt++)
                acc[tt] += band[tt][s] * wv;
        }
    }

    float* O = out + ((long long)(b * T_DIM + t0)) * ODIM + tid;
    #pragma unroll
    for (int tt = 0; tt < 10; tt++)
        O[tt * ODIM] = fmaxf(acc[tt], 0.f);
}

// ---------------------------------------------------------------------------
extern "C" void kernel_launch(void* const* d_in, const int* in_sizes, int n_in,
                              void* d_out, int out_size) {
    const int*   frames = (const int*)  d_in[0];
    const float* fc_w   = (const float*)d_in[1];
    const float* fc_b   = (const float*)d_in[2];
    float*       out    = (float*)d_out;

    float* hist;
    float* sim;
    cudaGetSymbolAddress((void**)&hist, g_hist);
    cudaGetSymbolAddress((void**)&sim,  g_sim);

    k_hist<<<B_DIM * T_DIM, 256>>>(frames, hist);
    k_sim <<<dim3(9, B_DIM), 256>>>(hist, sim);
    k_fc  <<<dim3(T_DIM / 10, B_DIM), 128>>>(sim, fc_w, fc_b, out);
}

// round 3
// speedup vs baseline: 1.1737x; 1.0504x over previous
#include <cuda_runtime.h>
#include <cuda_bf16.h>

// Problem constants
#define B_DIM 16
#define T_DIM 100
#define HW 1296           // 27*48
#define FRAME_INTS (HW*3) // 3888
#define NBINS 512
#define WIN 101
#define HALF 50
#define ODIM 128

// Scratch (device globals — no allocation allowed)
__device__ float g_hist[B_DIM * T_DIM * NBINS];   // 3.28 MB
__device__ float g_sim [B_DIM * T_DIM * T_DIM];   // 640 KB

// ---------------------------------------------------------------------------
// Kernel 1: per-frame 512-bin color histogram + L2 normalize
// At the smem-atomics (ATOMS) pipe floor: ~2.07M atomics / 148 SMs.
// ---------------------------------------------------------------------------
__global__ __launch_bounds__(256) void k_hist(const int* __restrict__ frames,
                                              float* __restrict__ hist) {
    __shared__ int sh[NBINS];
    __shared__ int wsum[8];
    __shared__ float s_inv;

    const int f   = blockIdx.x;
    const int tid = threadIdx.x;

    for (int i = tid; i < NBINS; i += 256) sh[i] = 0;
    __syncthreads();

    // 3888 ints = 972 int4 = 324 chunks of 3 int4 (4 pixels each)
    const int4* base = reinterpret_cast<const int4*>(frames + (long long)f * FRAME_INTS);
    for (int c = tid; c < 324; c += 256) {
        int4 a = base[3*c+0];
        int4 b = base[3*c+1];
        int4 d = base[3*c+2];
        int bin0 = ((a.x >> 5) << 6) | ((a.y >> 5) << 3) | (a.z >> 5);
        int bin1 = ((a.w >> 5) << 6) | ((b.x >> 5) << 3) | (b.y >> 5);
        int bin2 = ((b.z >> 5) << 6) | ((b.w >> 5) << 3) | (d.x >> 5);
        int bin3 = ((d.y >> 5) << 6) | ((d.z >> 5) << 3) | (d.w >> 5);
        atomicAdd(&sh[bin0], 1);
        atomicAdd(&sh[bin1], 1);
        atomicAdd(&sh[bin2], 1);
        atomicAdd(&sh[bin3], 1);
    }
    __syncthreads();

    // Exact integer sum of squares (<= 1296^2 < 2^31)
    int local = 0;
    for (int i = tid; i < NBINS; i += 256) { int h = sh[i]; local += h * h; }
    #pragma unroll
    for (int o = 16; o; o >>= 1) local += __shfl_down_sync(0xffffffff, local, o);
    if ((tid & 31) == 0) wsum[tid >> 5] = local;
    __syncthreads();
    if (tid == 0) {
        int tot = 0;
        #pragma unroll
        for (int w = 0; w < 8; w++) tot += wsum[w];
        s_inv = 1.0f / sqrtf((float)tot);
    }
    __syncthreads();

    const float inv = s_inv;
    float* out = hist + (long long)f * NBINS;
    for (int i = tid; i < NBINS; i += 256) out[i] = (float)sh[i] * inv;
}

// ---------------------------------------------------------------------------
// Kernel 2: sim[b] = X[b] @ X[b]^T  (X is 100x512), banded + symmetric.
// 32x32 tiles; ti<=tj only (symmetry), |ti-tj|==3 skipped (outside band).
// Warp w owns 4 output columns (broadcast float4 LDS from transposed B tile);
// lane owns one row (conflict-free scalar LDS from 33-padded A tile).
// Register-prefetch + double-buffered smem -> LDGs overlap compute.
// ---------------------------------------------------------------------------
__constant__ int c_ti[9] = {0,0,0,1,1,1,2,2,3};
__constant__ int c_tj[9] = {0,1,2,1,2,3,2,3,3};

__global__ __launch_bounds__(256) void k_sim(const float* __restrict__ hist,
                                             float* __restrict__ sim) {
    __shared__ float As [2][32][33];             // [buf][row][k]
    __shared__ __align__(16) float Bst[2][32][36]; // [buf][k][col]

    const int b  = blockIdx.y;
    const int ti = c_ti[blockIdx.x];
    const int tj = c_tj[blockIdx.x];

    const float* X = hist + (long long)b * T_DIM * NBINS;
    const int tid  = threadIdx.x;
    const int w    = tid >> 5;      // warp 0..7 -> cols 4w..4w+3
    const int lane = tid & 31;      // row within tile, and k-index for loads

    const int row0 = ti * 32;
    const int col0 = tj * 32;

    // Load slots: thread j-th slot handles tile-row (w + 8j), k = lane
    bool va[4], vb[4];
    const float* pa[4];
    const float* pb[4];
    #pragma unroll
    for (int j = 0; j < 4; j++) {
        int r = w + 8 * j;
        va[j] = (row0 + r) < T_DIM;
        vb[j] = (col0 + r) < T_DIM;
        pa[j] = X + (row0 + r) * NBINS + lane;
        pb[j] = X + (col0 + r) * NBINS + lane;
    }

    float ra[4], rb[4];
    #pragma unroll
    for (int j = 0; j < 4; j++) {
        ra[j] = va[j] ? pa[j][0] : 0.f;
        rb[j] = vb[j] ? pb[j][0] : 0.f;
    }
    #pragma unroll
    for (int j = 0; j < 4; j++) {
        As [0][w + 8*j][lane] = ra[j];
        Bst[0][lane][w + 8*j] = rb[j];
    }
    __syncthreads();

    float acc0 = 0.f, acc1 = 0.f, acc2 = 0.f, acc3 = 0.f;

    #pragma unroll 1
    for (int it = 0; it < 16; it++) {
        const int buf = it & 1;

        // Prefetch next k-tile into registers (LDGs in flight during compute)
        if (it < 15) {
            const int kc = (it + 1) * 32;
            #pragma unroll
            for (int j = 0; j < 4; j++) {
                ra[j] = va[j] ? pa[j][kc] : 0.f;
                rb[j] = vb[j] ? pb[j][kc] : 0.f;
            }
        }

        // Compute: per k -> 1 scalar LDS (A, conflict-free) + 1 broadcast
        // float4 LDS (B cols) + 4 FFMA. FMA-pipe-bound.
        const float* arow = &As[buf][lane][0];
        const float* bcol = &Bst[buf][0][4 * w];
        #pragma unroll
        for (int k = 0; k < 32; k++) {
            float a = arow[k];
            float4 bq = *reinterpret_cast<const float4*>(bcol + k * 36);
            acc0 += a * bq.x;
            acc1 += a * bq.y;
            acc2 += a * bq.z;
            acc3 += a * bq.w;
        }

        if (it < 15) {
            __syncthreads();   // everyone done reading buf^1
            #pragma unroll
            for (int j = 0; j < 4; j++) {
                As [buf ^ 1][w + 8*j][lane] = ra[j];
                Bst[buf ^ 1][lane][w + 8*j] = rb[j];
            }
            __syncthreads();   // next tile ready
        }
    }

    // Write-back with symmetry
    float* S = sim + (long long)b * T_DIM * T_DIM;
    const int r = row0 + lane;
    if (r < T_DIM) {
        float accs[4] = {acc0, acc1, acc2, acc3};
        #pragma unroll
        for (int q = 0; q < 4; q++) {
            int c = col0 + 4 * w + q;
            if (c < T_DIM) {
                S[r * T_DIM + c] = accs[q];
                S[c * T_DIM + r] = accs[q];
            }
        }
    }
}

// ---------------------------------------------------------------------------
// Kernel 3: band extraction + FC + ReLU
// Block = (batch, 10 consecutive t). 128 threads; thread owns output dim d.
// j-outer: 1 coalesced weight LDS + 10 broadcast band LDS per 10 FFMA.
// ---------------------------------------------------------------------------
__global__ __launch_bounds__(128) void k_fc(const float* __restrict__ sim,
                                            const float* __restrict__ fc_w,
                                            const float* __restrict__ fc_b,
                                            float* __restrict__ out) {
    __shared__ float w_s[51 * ODIM];     // 26112 B
    __shared__ float band[10][WIN];      //  4040 B

    const int b   = blockIdx.y;
    const int t0  = blockIdx.x * 10;
    const int tid = threadIdx.x;

    const float* S = sim + (long long)b * T_DIM * T_DIM;
    for (int i = tid; i < 10 * WIN; i += 128) {
        int tt = i / WIN, s = i - tt * WIN;
        int t  = t0 + tt;
        int t2 = t + s - HALF;
        band[tt][s] = (t2 >= 0 && t2 < T_DIM) ? S[t * T_DIM + t2] : 0.f;
    }

    float acc[10];
    const float bias = fc_b[tid];
    #pragma unroll
    for (int tt = 0; tt < 10; tt++) acc[tt] = bias;

    #pragma unroll
    for (int chunk = 0; chunk < 2; chunk++) {
        const int s0 = chunk ? 51 : 0;
        const int ns = chunk ? 50 : 51;
        __syncthreads();   // band ready (1st) / previous chunk compute done (2nd)
        for (int j = 0; j < ns; j++)
            w_s[j * ODIM + tid] = fc_w[(s0 + j) * ODIM + tid];
        __syncthreads();

        for (int j = 0; j < ns; j++) {
            const float wv = w_s[j * ODIM + tid];
            const int s = s0 + j;
            #pragma unroll
            for (int tt = 0; tt < 10; tt++)
                acc[tt] += band[tt][s] * wv;
        }
    }

    float* O = out + ((long long)(b * T_DIM + t0)) * ODIM + tid;
    #pragma unroll
    for (int tt = 0; tt < 10; tt++)
        O[tt * ODIM] = fmaxf(acc[tt], 0.f);
}

// ---------------------------------------------------------------------------
extern "C" void kernel_launch(void* const* d_in, const int* in_sizes, int n_in,
                              void* d_out, int out_size) {
    const int*   frames = (const int*)  d_in[0];
    const float* fc_w   = (const float*)d_in[1];
    const float* fc_b   = (const float*)d_in[2];
    float*       out    = (float*)d_out;

    float* hist;
    float* sim;
    cudaGetSymbolAddress((void**)&hist, g_hist);
    cudaGetSymbolAddress((void**)&sim,  g_sim);

    k_hist<<<B_DIM * T_DIM, 256>>>(frames, hist);
    k_sim <<<dim3(9, B_DIM), 256>>>(hist, sim);
    k_fc  <<<dim3(T_DIM / 10, B_DIM), 128>>>(sim, fc_w, fc_b, out);
}

// round 4
// speedup vs baseline: 1.3361x; 1.1383x over previous
#include <cuda_runtime.h>
#include <cuda_bf16.h>

// Problem constants
#define B_DIM 16
#define T_DIM 100
#define HW 1296           // 27*48
#define FRAME_INTS (HW*3) // 3888
#define NBINS 512
#define WIN 101
#define HALF 50
#define ODIM 128

// Scratch (device globals — no allocation allowed)
__device__ float g_hist[B_DIM * T_DIM * NBINS];   // 3.28 MB
__device__ float g_sim [B_DIM * T_DIM * T_DIM];   // 640 KB

// ---------------------------------------------------------------------------
// Kernel 1: per-frame 512-bin color histogram + L2 normalize.
// At the smem-atomics (ATOMS) pipe floor (~2.07M atomics / 148 SMs).
// ---------------------------------------------------------------------------
__global__ __launch_bounds__(256) void k_hist(const int* __restrict__ frames,
                                              float* __restrict__ hist) {
    __shared__ int sh[NBINS];
    __shared__ int wsum[8];
    __shared__ float s_inv;

    const int f   = blockIdx.x;
    const int tid = threadIdx.x;

    for (int i = tid; i < NBINS; i += 256) sh[i] = 0;
    __syncthreads();

    const int4* base = reinterpret_cast<const int4*>(frames + (long long)f * FRAME_INTS);
    for (int c = tid; c < 324; c += 256) {
        int4 a = base[3*c+0];
        int4 b = base[3*c+1];
        int4 d = base[3*c+2];
        int bin0 = ((a.x >> 5) << 6) | ((a.y >> 5) << 3) | (a.z >> 5);
        int bin1 = ((a.w >> 5) << 6) | ((b.x >> 5) << 3) | (b.y >> 5);
        int bin2 = ((b.z >> 5) << 6) | ((b.w >> 5) << 3) | (d.x >> 5);
        int bin3 = ((d.y >> 5) << 6) | ((d.z >> 5) << 3) | (d.w >> 5);
        atomicAdd(&sh[bin0], 1);
        atomicAdd(&sh[bin1], 1);
        atomicAdd(&sh[bin2], 1);
        atomicAdd(&sh[bin3], 1);
    }
    __syncthreads();

    int local = 0;
    for (int i = tid; i < NBINS; i += 256) { int h = sh[i]; local += h * h; }
    #pragma unroll
    for (int o = 16; o; o >>= 1) local += __shfl_down_sync(0xffffffff, local, o);
    if ((tid & 31) == 0) wsum[tid >> 5] = local;
    __syncthreads();
    if (tid == 0) {
        int tot = 0;
        #pragma unroll
        for (int w = 0; w < 8; w++) tot += wsum[w];
        s_inv = 1.0f / sqrtf((float)tot);
    }
    __syncthreads();

    const float inv = s_inv;
    float* out = hist + (long long)f * NBINS;
    for (int i = tid; i < NBINS; i += 256) out[i] = (float)sh[i] * inv;
}

// ---------------------------------------------------------------------------
// Kernel 2: sim[b] = X[b] @ X[b]^T, banded + symmetric.
// 512 threads: warps 0-7 accumulate k in [0,256), warps 8-15 k in [256,512)
// (k-split -> 4 warps/SMSP, hides LDS/LDG latency). Double-buffered smem,
// register prefetch. float4 A reads (36-pad). smem combine of the two halves.
// ---------------------------------------------------------------------------
__constant__ int c_ti[9] = {0,0,0,1,1,1,2,2,3};
__constant__ int c_tj[9] = {0,1,2,1,2,3,2,3,3};

__global__ __launch_bounds__(512) void k_sim(const float* __restrict__ hist,
                                             float* __restrict__ sim) {
    __shared__ __align__(16) float As [2][2][32][36]; // [half][buf][row][k]
    __shared__ __align__(16) float Bst[2][2][32][36]; // [half][buf][k][col]
    __shared__ float red[4][256];

    const int b  = blockIdx.y;
    const int ti = c_ti[blockIdx.x];
    const int tj = c_tj[blockIdx.x];

    const float* X = hist + (long long)b * T_DIM * NBINS;
    const int tid  = threadIdx.x;
    const int half = tid >> 8;        // k-half
    const int t2   = tid & 255;
    const int w    = t2 >> 5;         // warp-in-half: cols 4w..4w+3
    const int lane = t2 & 31;         // row within tile / k-index for loads

    const int row0 = ti * 32;
    const int col0 = tj * 32;
    const int kbase = half * 256;

    bool va[4], vb[4];
    const float* pa[4];
    const float* pb[4];
    #pragma unroll
    for (int j = 0; j < 4; j++) {
        int r = w + 8 * j;
        va[j] = (row0 + r) < T_DIM;
        vb[j] = (col0 + r) < T_DIM;
        pa[j] = X + (row0 + r) * NBINS + kbase + lane;
        pb[j] = X + (col0 + r) * NBINS + kbase + lane;
    }

    float ra[4], rb[4];
    #pragma unroll
    for (int j = 0; j < 4; j++) {
        ra[j] = va[j] ? pa[j][0] : 0.f;
        rb[j] = vb[j] ? pb[j][0] : 0.f;
    }
    #pragma unroll
    for (int j = 0; j < 4; j++) {
        As [half][0][w + 8*j][lane] = ra[j];
        Bst[half][0][lane][w + 8*j] = rb[j];
    }
    __syncthreads();

    float acc0 = 0.f, acc1 = 0.f, acc2 = 0.f, acc3 = 0.f;

    #pragma unroll 1
    for (int it = 0; it < 8; it++) {
        const int buf = it & 1;

        if (it < 7) {
            const int kc = (it + 1) * 32;
            #pragma unroll
            for (int j = 0; j < 4; j++) {
                ra[j] = va[j] ? pa[j][kc] : 0.f;
                rb[j] = vb[j] ? pb[j][kc] : 0.f;
            }
        }

        const float* arow = &As[half][buf][lane][0];
        const float* bcol = &Bst[half][buf][0][4 * w];
        #pragma unroll
        for (int k4 = 0; k4 < 8; k4++) {
            float4 a4 = *reinterpret_cast<const float4*>(arow + 4 * k4);
            float av[4] = {a4.x, a4.y, a4.z, a4.w};
            #pragma unroll
            for (int u = 0; u < 4; u++) {
                float4 bq = *reinterpret_cast<const float4*>(bcol + (4*k4 + u) * 36);
                acc0 += av[u] * bq.x;
                acc1 += av[u] * bq.y;
                acc2 += av[u] * bq.z;
                acc3 += av[u] * bq.w;
            }
        }

        if (it < 7) {
            __syncthreads();
            #pragma unroll
            for (int j = 0; j < 4; j++) {
                As [half][buf ^ 1][w + 8*j][lane] = ra[j];
                Bst[half][buf ^ 1][lane][w + 8*j] = rb[j];
            }
            __syncthreads();
        }
    }

    // Combine the two k-halves
    if (half == 1) {
        red[0][t2] = acc0; red[1][t2] = acc1;
        red[2][t2] = acc2; red[3][t2] = acc3;
    }
    __syncthreads();

    if (half == 0) {
        acc0 += red[0][t2]; acc1 += red[1][t2];
        acc2 += red[2][t2]; acc3 += red[3][t2];

        float* S = sim + (long long)b * T_DIM * T_DIM;
        const int r = row0 + lane;
        if (r < T_DIM) {
            float accs[4] = {acc0, acc1, acc2, acc3};
            #pragma unroll
            for (int q = 0; q < 4; q++) {
                int c = col0 + 4 * w + q;
                if (c < T_DIM) {
                    S[r * T_DIM + c] = accs[q];
                    S[c * T_DIM + r] = accs[q];
                }
            }
        }
    }
}

// ---------------------------------------------------------------------------
// Kernel 3: band extraction + FC + ReLU.
// 256 threads: tid = d + 128*h. h=0 handles s in [0,51), h=1 s in [51,101)
// (disjoint weight rows). Full 101x128 weights in dynamic smem (61KB).
// smem combine of the two s-halves, then bias + ReLU + store.
// ---------------------------------------------------------------------------
#define FC_W_FLOATS  (WIN * ODIM)        // 12928
#define FC_BAND_OFF  FC_W_FLOATS
#define FC_SCR_OFF   (FC_W_FLOATS + 10 * WIN)
#define FC_SMEM_FLOATS (FC_SCR_OFF + 10 * ODIM)
#define FC_SMEM_BYTES  (FC_SMEM_FLOATS * 4)

__global__ __launch_bounds__(256) void k_fc(const float* __restrict__ sim,
                                            const float* __restrict__ fc_w,
                                            const float* __restrict__ fc_b,
                                            float* __restrict__ out) {
    extern __shared__ __align__(16) float dyn[];
    float* w_s  = dyn;                 // [101][128]
    float* band = dyn + FC_BAND_OFF;   // [10][101]
    float* scr  = dyn + FC_SCR_OFF;    // [10][128]

    const int b   = blockIdx.y;
    const int t0  = blockIdx.x * 10;
    const int tid = threadIdx.x;
    const int d   = tid & 127;
    const int h   = tid >> 7;

    // Weights: 3232 float4 copies, coalesced
    {
        const float4* src = reinterpret_cast<const float4*>(fc_w);
        float4* dst = reinterpret_cast<float4*>(w_s);
        for (int i = tid; i < FC_W_FLOATS / 4; i += 256) dst[i] = src[i];
    }

    // Band rows for the 10 t's (zero outside [0,100))
    const float* S = sim + (long long)b * T_DIM * T_DIM;
    for (int i = tid; i < 10 * WIN; i += 256) {
        int tt = i / WIN, s = i - tt * WIN;
        int t  = t0 + tt;
        int s2 = t + s - HALF;
        band[tt * WIN + s] = (s2 >= 0 && s2 < T_DIM) ? S[t * T_DIM + s2] : 0.f;
    }
    __syncthreads();

    const int s0 = h ? 51 : 0;
    const int ns = h ? 50 : 51;

    float acc[10];
    #pragma unroll
    for (int tt = 0; tt < 10; tt++) acc[tt] = 0.f;

    for (int j = 0; j < ns; j++) {
        const float wv = w_s[(s0 + j) * ODIM + d];
        const int s = s0 + j;
        #pragma unroll
        for (int tt = 0; tt < 10; tt++)
            acc[tt] += band[tt * WIN + s] * wv;
    }

    if (h == 1) {
        #pragma unroll
        for (int tt = 0; tt < 10; tt++) scr[tt * ODIM + d] = acc[tt];
    }
    __syncthreads();

    if (h == 0) {
        const float bias = fc_b[d];
        float* O = out + ((long long)(b * T_DIM + t0)) * ODIM + d;
        #pragma unroll
        for (int tt = 0; tt < 10; tt++) {
            float v = acc[tt] + scr[tt * ODIM + d] + bias;
            O[tt * ODIM] = fmaxf(v, 0.f);
        }
    }
}

// ---------------------------------------------------------------------------
extern "C" void kernel_launch(void* const* d_in, const int* in_sizes, int n_in,
                              void* d_out, int out_size) {
    const int*   frames = (const int*)  d_in[0];
    const float* fc_w   = (const float*)d_in[1];
    const float* fc_b   = (const float*)d_in[2];
    float*       out    = (float*)d_out;

    float* hist;
    float* sim;
    cudaGetSymbolAddress((void**)&hist, g_hist);
    cudaGetSymbolAddress((void**)&sim,  g_sim);

    cudaFuncSetAttribute(k_fc, cudaFuncAttributeMaxDynamicSharedMemorySize,
                         FC_SMEM_BYTES);

    k_hist<<<B_DIM * T_DIM, 256>>>(frames, hist);
    k_sim <<<dim3(9, B_DIM), 512>>>(hist, sim);
    k_fc  <<<dim3(T_DIM / 10, B_DIM), 256, FC_SMEM_BYTES>>>(sim, fc_w, fc_b, out);
}

// round 5
// speedup vs baseline: 1.6485x; 1.2339x over previous
#include <cuda_runtime.h>
#include <cuda_bf16.h>

// Problem constants
#define B_DIM 16
#define T_DIM 100
#define HW 1296           // 27*48
#define FRAME_INTS (HW*3) // 3888
#define NBINS 512
#define WIN 101
#define HALF 50
#define ODIM 128

// Scratch (device globals — no allocation allowed)
__device__ float g_hist[B_DIM * T_DIM * NBINS];   // 3.28 MB
__device__ float g_sim [B_DIM * T_DIM * T_DIM];   // 640 KB

// ---- f32x2 packed-FMA helpers (FFMA2: 2 FMA per instr, only via PTX) ------
__device__ __forceinline__ void ffma2(unsigned long long& d,
                                      unsigned long long a,
                                      unsigned long long b) {
    asm("fma.rn.f32x2 %0, %1, %2, %0;" : "+l"(d) : "l"(a), "l"(b));
}
__device__ __forceinline__ float2 f2unpack(unsigned long long u) {
    float2 f;
    asm("mov.b64 {%0, %1}, %2;" : "=f"(f.x), "=f"(f.y) : "l"(u));
    return f;
}
__device__ __forceinline__ unsigned long long f2pack(float a, float b) {
    unsigned long long u;
    asm("mov.b64 %0, {%1, %2};" : "=l"(u) : "f"(a), "f"(b));
    return u;
}

// ---------------------------------------------------------------------------
// Kernel 1: per-frame 512-bin color histogram + L2 normalize.
// At the smem-atomics (ATOMS) pipe floor (~2.07M atomics / 148 SMs).
// ---------------------------------------------------------------------------
__global__ __launch_bounds__(256) void k_hist(const int* __restrict__ frames,
                                              float* __restrict__ hist) {
    __shared__ int sh[NBINS];
    __shared__ int wsum[8];
    __shared__ float s_inv;

    const int f   = blockIdx.x;
    const int tid = threadIdx.x;

    for (int i = tid; i < NBINS; i += 256) sh[i] = 0;
    __syncthreads();

    const int4* base = reinterpret_cast<const int4*>(frames + (long long)f * FRAME_INTS);
    for (int c = tid; c < 324; c += 256) {
        int4 a = base[3*c+0];
        int4 b = base[3*c+1];
        int4 d = base[3*c+2];
        int bin0 = ((a.x >> 5) << 6) | ((a.y >> 5) << 3) | (a.z >> 5);
        int bin1 = ((a.w >> 5) << 6) | ((b.x >> 5) << 3) | (b.y >> 5);
        int bin2 = ((b.z >> 5) << 6) | ((b.w >> 5) << 3) | (d.x >> 5);
        int bin3 = ((d.y >> 5) << 6) | ((d.z >> 5) << 3) | (d.w >> 5);
        atomicAdd(&sh[bin0], 1);
        atomicAdd(&sh[bin1], 1);
        atomicAdd(&sh[bin2], 1);
        atomicAdd(&sh[bin3], 1);
    }
    __syncthreads();

    int local = 0;
    for (int i = tid; i < NBINS; i += 256) { int h = sh[i]; local += h * h; }
    #pragma unroll
    for (int o = 16; o; o >>= 1) local += __shfl_down_sync(0xffffffff, local, o);
    if ((tid & 31) == 0) wsum[tid >> 5] = local;
    __syncthreads();
    if (tid == 0) {
        int tot = 0;
        #pragma unroll
        for (int w = 0; w < 8; w++) tot += wsum[w];
        s_inv = 1.0f / sqrtf((float)tot);
    }
    __syncthreads();

    const float inv = s_inv;
    float* out = hist + (long long)f * NBINS;
    for (int i = tid; i < NBINS; i += 256) out[i] = (float)sh[i] * inv;
}

// ---------------------------------------------------------------------------
// Kernel 2: sim[b] = X[b] @ X[b]^T, banded + symmetric.
// Fully smem-resident 32x32x512 tile GEMM. 512 threads, 2 barriers total.
// 16 warps = 4 k-quarters x 4 col-groups. Lane: rows {lane&15, +16},
// cols 8*wc + 4*(lane>>4) .. +3. f32x2 FMA with k-pair accumulation
// (both operand pairs are u64 halves of float4 smem loads -> no packing).
// ---------------------------------------------------------------------------
__constant__ int c_ti[9] = {0,0,0,1,1,1,2,2,3};
__constant__ int c_tj[9] = {0,1,2,1,2,3,2,3,3};

#define AS_STRIDE 516                       // 512 + 4 pad (conflict-free, 16B aligned)
#define SIM_SMEM_FLOATS (2*32*AS_STRIDE + 4*32*36)
#define SIM_SMEM_BYTES  (SIM_SMEM_FLOATS * 4)   // 150528

__global__ __launch_bounds__(512) void k_sim(const float* __restrict__ hist,
                                             float* __restrict__ sim) {
    extern __shared__ __align__(16) float sm[];
    float* A_s = sm;                         // [32][516]
    float* B_s = sm + 32 * AS_STRIDE;        // [32][516]
    float* red = sm + 64 * AS_STRIDE;        // [4][32][36]

    const int b  = blockIdx.y;
    const int ti = c_ti[blockIdx.x];
    const int tj = c_tj[blockIdx.x];
    const int row0 = ti * 32;
    const int col0 = tj * 32;
    const float* X = hist + (long long)b * T_DIM * NBINS;
    const int tid = threadIdx.x;

    // Load both 32x512 tiles (float4 coalesced; zero-fill rows >= 100)
    #pragma unroll
    for (int i = tid; i < 4096; i += 512) {
        int row = i >> 7;
        int k   = (i & 127) << 2;
        float4 va = make_float4(0.f, 0.f, 0.f, 0.f);
        float4 vb = va;
        int gr = row0 + row, gc = col0 + row;
        if (gr < T_DIM) va = *reinterpret_cast<const float4*>(X + gr * NBINS + k);
        if (gc < T_DIM) vb = *reinterpret_cast<const float4*>(X + gc * NBINS + k);
        *reinterpret_cast<float4*>(A_s + row * AS_STRIDE + k) = va;
        *reinterpret_cast<float4*>(B_s + row * AS_STRIDE + k) = vb;
    }
    __syncthreads();

    const int w    = tid >> 5;
    const int lane = tid & 31;
    const int q    = w >> 2;          // k-quarter: k in [128q, 128q+128)
    const int wc   = w & 3;           // col-group
    const int r0   = lane & 15;       // rows r0 and r0+16
    const int rh   = lane >> 4;       // col sub-group
    const int cb   = 8 * wc + 4 * rh; // cols cb..cb+3
    const int kb   = 128 * q;

    unsigned long long acc[8];
    #pragma unroll
    for (int i = 0; i < 8; i++) acc[i] = 0ull;

    const float* a0 = A_s + r0 * AS_STRIDE + kb;
    const float* a1 = a0 + 16 * AS_STRIDE;
    const float* b0 = B_s + (cb + 0) * AS_STRIDE + kb;
    const float* b1 = b0 + AS_STRIDE;
    const float* b2 = b1 + AS_STRIDE;
    const float* b3 = b2 + AS_STRIDE;

    #pragma unroll 4
    for (int k = 0; k < 128; k += 4) {
        ulonglong2 aL = *reinterpret_cast<const ulonglong2*>(a0 + k);
        ulonglong2 aH = *reinterpret_cast<const ulonglong2*>(a1 + k);
        ulonglong2 q0 = *reinterpret_cast<const ulonglong2*>(b0 + k);
        ulonglong2 q1 = *reinterpret_cast<const ulonglong2*>(b1 + k);
        ulonglong2 q2 = *reinterpret_cast<const ulonglong2*>(b2 + k);
        ulonglong2 q3 = *reinterpret_cast<const ulonglong2*>(b3 + k);

        ffma2(acc[0], aL.x, q0.x); ffma2(acc[0], aL.y, q0.y);
        ffma2(acc[1], aL.x, q1.x); ffma2(acc[1], aL.y, q1.y);
        ffma2(acc[2], aL.x, q2.x); ffma2(acc[2], aL.y, q2.y);
        ffma2(acc[3], aL.x, q3.x); ffma2(acc[3], aL.y, q3.y);
        ffma2(acc[4], aH.x, q0.x); ffma2(acc[4], aH.y, q0.y);
        ffma2(acc[5], aH.x, q1.x); ffma2(acc[5], aH.y, q1.y);
        ffma2(acc[6], aH.x, q2.x); ffma2(acc[6], aH.y, q2.y);
        ffma2(acc[7], aH.x, q3.x); ffma2(acc[7], aH.y, q3.y);
    }

    // Partial sums per k-quarter into smem
    #pragma unroll
    for (int rr = 0; rr < 2; rr++) {
        #pragma unroll
        for (int cc = 0; cc < 4; cc++) {
            float2 f = f2unpack(acc[rr * 4 + cc]);
            red[(q * 32 + r0 + 16 * rr) * 36 + cb + cc] = f.x + f.y;
        }
    }
    __syncthreads();

    // Combine quarters + write with symmetry (2 outputs per thread)
    float* S = sim + (long long)b * T_DIM * T_DIM;
    #pragma unroll
    for (int j = 0; j < 2; j++) {
        int o = tid + j * 512;
        int r = o >> 5, c = o & 31;
        float v = red[(r     ) * 36 + c] + red[(32 + r) * 36 + c]
                + red[(64 + r) * 36 + c] + red[(96 + r) * 36 + c];
        int gr = row0 + r, gc = col0 + c;
        if (gr < T_DIM && gc < T_DIM) {
            S[gr * T_DIM + gc] = v;
            S[gc * T_DIM + gr] = v;
        }
    }
}

// ---------------------------------------------------------------------------
// Kernel 3: band extraction + FC + ReLU.
// 256 threads: tid = d + 128*h; h=0 s in [0,52), h=1 s in [52,101).
// Band stored transposed [s][tt] -> per j: 3 vector broadcasts + 5 FFMA2.
// ---------------------------------------------------------------------------
#define FC_W_FLOATS  (WIN * ODIM)             // 12928
#define FC_BT_OFF    FC_W_FLOATS              // band_t [104][12]
#define FC_SCR_OFF   (FC_W_FLOATS + 104 * 12)
#define FC_SMEM_FLOATS (FC_SCR_OFF + 10 * ODIM)
#define FC_SMEM_BYTES  (FC_SMEM_FLOATS * 4)

__global__ __launch_bounds__(256) void k_fc(const float* __restrict__ sim,
                                            const float* __restrict__ fc_w,
                                            const float* __restrict__ fc_b,
                                            float* __restrict__ out) {
    extern __shared__ __align__(16) float dyn[];
    float* w_s    = dyn;                 // [101][128]
    float* band_t = dyn + FC_BT_OFF;     // [s up to 104][12] (tt 0..9 used)
    float* scr    = dyn + FC_SCR_OFF;    // [10][128]

    const int b   = blockIdx.y;
    const int t0  = blockIdx.x * 10;
    const int tid = threadIdx.x;
    const int d   = tid & 127;
    const int h   = tid >> 7;

    // Weights: coalesced float4
    {
        const float4* src = reinterpret_cast<const float4*>(fc_w);
        float4* dst = reinterpret_cast<float4*>(w_s);
        for (int i = tid; i < FC_W_FLOATS / 4; i += 256) dst[i] = src[i];
    }

    // Band rows, stored transposed: band_t[s][tt]
    const float* S = sim + (long long)b * T_DIM * T_DIM;
    for (int i = tid; i < 10 * WIN; i += 256) {
        int tt = i / WIN, s = i - tt * WIN;
        int t  = t0 + tt;
        int t2 = t + s - HALF;
        band_t[s * 12 + tt] = (t2 >= 0 && t2 < T_DIM) ? S[t * T_DIM + t2] : 0.f;
    }
    __syncthreads();

    const int s0 = h ? 52 : 0;
    const int ns = h ? 49 : 52;

    unsigned long long acc2[5];
    #pragma unroll
    for (int i = 0; i < 5; i++) acc2[i] = 0ull;

    const float* wp = w_s + d;
    for (int j = 0; j < ns; j++) {
        const int s = s0 + j;
        float wv = wp[s * ODIM];
        unsigned long long ww = f2pack(wv, wv);
        const float* bt = band_t + s * 12;
        ulonglong2 p01 = *reinterpret_cast<const ulonglong2*>(bt);       // tt 0-3
        ulonglong2 p23 = *reinterpret_cast<const ulonglong2*>(bt + 4);   // tt 4-7
        unsigned long long p4 = *reinterpret_cast<const unsigned long long*>(bt + 8); // tt 8-9
        ffma2(acc2[0], ww, p01.x);
        ffma2(acc2[1], ww, p01.y);
        ffma2(acc2[2], ww, p23.x);
        ffma2(acc2[3], ww, p23.y);
        ffma2(acc2[4], ww, p4);
    }

    float acc[10];
    #pragma unroll
    for (int p = 0; p < 5; p++) {
        float2 f = f2unpack(acc2[p]);
        acc[2 * p]     = f.x;
        acc[2 * p + 1] = f.y;
    }

    if (h == 1) {
        #pragma unroll
        for (int tt = 0; tt < 10; tt++) scr[tt * ODIM + d] = acc[tt];
    }
    __syncthreads();

    if (h == 0) {
        const float bias = fc_b[d];
        float* O = out + ((long long)(b * T_DIM + t0)) * ODIM + d;
        #pragma unroll
        for (int tt = 0; tt < 10; tt++) {
            float v = acc[tt] + scr[tt * ODIM + d] + bias;
            O[tt * ODIM] = fmaxf(v, 0.f);
        }
    }
}

// ---------------------------------------------------------------------------
extern "C" void kernel_launch(void* const* d_in, const int* in_sizes, int n_in,
                              void* d_out, int out_size) {
    const int*   frames = (const int*)  d_in[0];
    const float* fc_w   = (const float*)d_in[1];
    const float* fc_b   = (const float*)d_in[2];
    float*       out    = (float*)d_out;

    float* hist;
    float* sim;
    cudaGetSymbolAddress((void**)&hist, g_hist);
    cudaGetSymbolAddress((void**)&sim,  g_sim);

    cudaFuncSetAttribute(k_sim, cudaFuncAttributeMaxDynamicSharedMemorySize,
                         SIM_SMEM_BYTES);
    cudaFuncSetAttribute(k_fc, cudaFuncAttributeMaxDynamicSharedMemorySize,
                         FC_SMEM_BYTES);

    k_hist<<<B_DIM * T_DIM, 256>>>(frames, hist);
    k_sim <<<dim3(9, B_DIM), 512, SIM_SMEM_BYTES>>>(hist, sim);
    k_fc  <<<dim3(T_DIM / 10, B_DIM), 256, FC_SMEM_BYTES>>>(sim, fc_w, fc_b, out);
}